// round 13
// baseline (speedup 1.0000x reference)
#include <cuda_runtime.h>
#include <math.h>

#define NB 1024
#define EPSV 1e-8f
#define QCAP 65536
#define CAPB 2048
#define NBINS 128
#define INVW (128.0f / 80.0f)
#define RMAX 3.55f
#define GEN_BLOCKS 128
#define SWCAP 6144

struct BP {
    float cx, cy, area, vol;
    float cr, sr, hdx, hdy;
    float zlo, zhi;
    float corx[4];
    float cory[4];
};

struct MC { unsigned mask[32 * NB]; int ctr; };

__device__ MC g_mc;                    // suppression mask (orig space) + row-pair counter
__device__ unsigned g_qr[QCAP];        // row pairs (pred r, gt j) orig
__device__ unsigned long long g_rvkey[QCAP];

__device__ __forceinline__ void make_bp(BP& p, const float* b) {
    float x = b[0], y = b[1], z = b[2];
    float dx = b[3], dy = b[4], dz = b[5];
    float cr, sr;
    sincosf(b[6], &sr, &cr);
    p.cx = x; p.cy = y; p.cr = cr; p.sr = sr;
    p.hdx = 0.5f * dx; p.hdy = 0.5f * dy;
    p.area = dx * dy;
    p.vol = dx * dy * dz;
    p.zlo = z - 0.5f * dz; p.zhi = z + 0.5f * dz;
    const float sx[4] = {0.5f, 0.5f, -0.5f, -0.5f};
    const float sy[4] = {0.5f, -0.5f, -0.5f, 0.5f};
#pragma unroll
    for (int c = 0; c < 4; c++) {
        float lx = sx[c] * dx, ly = sy[c] * dy;
        p.corx[c] = lx * cr - ly * sr + x;
        p.cory[c] = lx * sr + ly * cr + y;
    }
}

__device__ __forceinline__ unsigned okey(float y, float x, int idx, unsigned msk) {
    float d = fabsf(x) + fabsf(y);
    float a = (d == 0.0f) ? 0.0f : copysignf(1.0f - x / d, y);
    unsigned u = __float_as_uint(a);
    u ^= (u & 0x80000000u) ? 0xFFFFFFFFu : 0x80000000u;
    return (u & msk) | (unsigned)idx;
}

// Reference-faithful rotated-rect intersection; tiered register bitonic sort.
__device__ float inter_area(const BP& A, const BP& B) {
    float px[24], py[24];
    int m = 0;
#pragma unroll
    for (int c = 0; c < 4; c++) {
        float dx = A.corx[c] - B.cx, dy = A.cory[c] - B.cy;
        float lx = dx * B.cr + dy * B.sr;
        float ly = -dx * B.sr + dy * B.cr;
        if (fabsf(lx) <= B.hdx + 1e-5f && fabsf(ly) <= B.hdy + 1e-5f) {
            px[m] = A.corx[c]; py[m] = A.cory[c]; m++;
        }
    }
#pragma unroll
    for (int c = 0; c < 4; c++) {
        float dx = B.corx[c] - A.cx, dy = B.cory[c] - A.cy;
        float lx = dx * A.cr + dy * A.sr;
        float ly = -dx * A.sr + dy * A.cr;
        if (fabsf(lx) <= A.hdx + 1e-5f && fabsf(ly) <= A.hdy + 1e-5f) {
            px[m] = B.corx[c]; py[m] = B.cory[c]; m++;
        }
    }
#pragma unroll
    for (int i = 0; i < 4; i++) {
        int i1 = (i + 1) & 3;
        float a0x = A.corx[i], a0y = A.cory[i];
        float d1x = A.corx[i1] - a0x, d1y = A.cory[i1] - a0y;
#pragma unroll
        for (int j = 0; j < 4; j++) {
            int j1 = (j + 1) & 3;
            float b0x = B.corx[j], b0y = B.cory[j];
            float d2x = B.corx[j1] - b0x, d2y = B.cory[j1] - b0y;
            float r0x = b0x - a0x, r0y = b0y - a0y;
            float den = d1x * d2y - d1y * d2x;
            if (fabsf(den) > EPSV) {
                float t = (r0x * d2y - r0y * d2x) / den;
                float u = (r0x * d1y - r0y * d1x) / den;
                if (t >= 0.f && t <= 1.f && u >= 0.f && u <= 1.f) {
                    px[m] = a0x + t * d1x; py[m] = a0y + t * d1y; m++;
                }
            }
        }
    }
    if (m < 3) return 0.0f;
    float sx = 0.f, sy = 0.f;
    for (int i = 0; i < m; i++) { sx += px[i]; sy += py[i]; }
    float inv = 1.0f / (float)m;
    float ctx = sx * inv, cty = sy * inv;
    float s = 0.f;

    if (m <= 16) {
        unsigned K[16];
#pragma unroll
        for (int i = 0; i < 16; i++)
            K[i] = (i < m) ? okey(py[i] - cty, px[i] - ctx, i, 0xFFFFFFF0u)
                           : (0xFFFFFFF0u | (unsigned)i);
#pragma unroll
        for (int kk = 2; kk <= 16; kk <<= 1)
#pragma unroll
            for (int jj = kk >> 1; jj > 0; jj >>= 1)
#pragma unroll
                for (int ii = 0; ii < 16; ii++) {
                    int ll = ii ^ jj;
                    if (ll > ii) {
                        bool up = ((ii & kk) == 0);
                        unsigned a2 = K[ii], b2 = K[ll];
                        if (up ? (a2 > b2) : (a2 < b2)) { K[ii] = b2; K[ll] = a2; }
                    }
                }
        int id0 = K[0] & 15;
        float x0 = px[id0] - ctx, y0 = py[id0] - cty;
        float xi = x0, yi = y0;
#pragma unroll
        for (int i = 0; i < 16; i++) {
            if (i < m) {
                float xj, yj;
                if (i + 1 < m) {
                    int idn = K[i + 1] & 15;
                    xj = px[idn] - ctx; yj = py[idn] - cty;
                } else { xj = x0; yj = y0; }
                s += xi * yj - yi * xj;
                xi = xj; yi = yj;
            }
        }
    } else {
        unsigned K[32];
#pragma unroll
        for (int i = 0; i < 32; i++)
            K[i] = (i < 24 && i < m) ? okey(py[i] - cty, px[i] - ctx, i, 0xFFFFFFE0u)
                                     : (0xFFFFFFE0u | (unsigned)i);
#pragma unroll
        for (int kk = 2; kk <= 32; kk <<= 1)
#pragma unroll
            for (int jj = kk >> 1; jj > 0; jj >>= 1)
#pragma unroll
                for (int ii = 0; ii < 32; ii++) {
                    int ll = ii ^ jj;
                    if (ll > ii) {
                        bool up = ((ii & kk) == 0);
                        unsigned a2 = K[ii], b2 = K[ll];
                        if (up ? (a2 > b2) : (a2 < b2)) { K[ii] = b2; K[ll] = a2; }
                    }
                }
        int id0 = K[0] & 31;
        float x0 = px[id0] - ctx, y0 = py[id0] - cty;
        float xi = x0, yi = y0;
#pragma unroll
        for (int i = 0; i < 24; i++) {
            if (i < m) {
                float xj, yj;
                if (i + 1 < m) {
                    int idn = K[i + 1] & 31;
                    xj = px[idn] - ctx; yj = py[idn] - cty;
                } else { xj = x0; yj = y0; }
                s += xi * yj - yi * xj;
                xi = xj; yi = yj;
            }
        }
    }
    return 0.5f * fabsf(s);
}

// ---------- k1: trivial outputs + binned pair gen + fused heavy compute ----------
__global__ void k1(const float* __restrict__ labels,
                   const float* __restrict__ pred,
                   const float* __restrict__ gt,
                   const float* __restrict__ cls,
                   float* __restrict__ out) {
    __shared__ __align__(16) unsigned char sbuf[16384 + 2 * CAPB * 4];
    __shared__ int shist[NBINS];
    __shared__ int scur[NBINS];
    __shared__ int sqn[2];
    __shared__ int sbase1;
    int b = blockIdx.x;
    int tid = threadIdx.x;

    if (b < 4) {
        int t = b * 256 + tid;
        float sgm = 1.0f / (1.0f + expf(-cls[t]));
        float lb = labels[t];
        out[t] = (sgm > 0.55f && lb > 0.55f) ? 1.0f : 0.0f;
        out[NB + t] = lb;
    }

    float4* sgt = (float4*)sbuf;
    unsigned* sq0 = (unsigned*)(sbuf + 16384);
    unsigned* sq1 = sq0 + CAPB;
    const float4* gt4 = (const float4*)gt;
    float4 st[4]; int sbin[4];
    if (tid < NBINS) shist[tid] = 0;
    if (tid < 2) sqn[tid] = 0;
    __syncthreads();
#pragma unroll
    for (int k = 0; k < 4; k++) {
        int i = tid + k * 256;
        float4 lo = gt4[2 * i];
        float4 hi = gt4[2 * i + 1];
        float rad = 0.5f * sqrtf(lo.w * lo.w + hi.x * hi.x) + 1e-3f;
        st[k] = make_float4(lo.x, lo.y, rad, __int_as_float(i));
        int bn = (int)((lo.x + 40.0f) * INVW);
        bn = min(max(bn, 0), NBINS - 1);
        sbin[k] = bn;
        atomicAdd(&shist[bn], 1);
    }
    __syncthreads();
    if (tid < 32) {
        int c0 = shist[tid * 4], c1 = shist[tid * 4 + 1];
        int c2 = shist[tid * 4 + 2], c3 = shist[tid * 4 + 3];
        int tot = c0 + c1 + c2 + c3;
        int pre = tot;
#pragma unroll
        for (int d = 1; d < 32; d <<= 1) {
            int v = __shfl_up_sync(0xffffffffu, pre, d);
            if (tid >= d) pre += v;
        }
        pre -= tot;
        shist[tid * 4] = pre;          scur[tid * 4] = pre;
        shist[tid * 4 + 1] = pre + c0; scur[tid * 4 + 1] = pre + c0;
        shist[tid * 4 + 2] = pre + c0 + c1; scur[tid * 4 + 2] = pre + c0 + c1;
        shist[tid * 4 + 3] = pre + c0 + c1 + c2; scur[tid * 4 + 3] = pre + c0 + c1 + c2;
    }
    __syncthreads();
#pragma unroll
    for (int k = 0; k < 4; k++) {
        int pos = atomicAdd(&scur[sbin[k]], 1);
        sgt[pos] = st[k];
    }
    __syncthreads();

    int lane = tid & 31;
#pragma unroll
    for (int tk = 0; tk < 2; tk++) {
        int task = (b * 8 + (tid >> 5)) * 2 + tk;
        int isrow = task >> 10;
        int i = task & 1023;
        float ax, ay, ar;
        if (isrow) {
            const float* p = pred + i * 7;
            ax = p[0]; ay = p[1];
            ar = 0.5f * sqrtf(p[3] * p[3] + p[4] * p[4]) + 1e-3f;
        } else {
            float4 lo = gt4[2 * i];
            float4 hi = gt4[2 * i + 1];
            ax = lo.x; ay = lo.y;
            ar = 0.5f * sqrtf(lo.w * lo.w + hi.x * hi.x) + 1e-3f;
        }
        float reach = ar + RMAX;
        int blo = max(0, (int)((ax - reach + 40.0f) * INVW));
        int bhi = min(NBINS - 1, (int)((ax + reach + 40.0f) * INVW));
        int pstart = shist[blo];
        int pend = (bhi == NBINS - 1) ? NB : shist[bhi + 1];
        unsigned ibits = (unsigned)i << 10;
        for (int p2 = pstart + lane; p2 < pend; p2 += 32) {
            float4 bb = sgt[p2];
            float ddx = ax - bb.x, ddy = ay - bb.y;
            float rs = ar + bb.z;
            int jorig = __float_as_int(bb.w);
            bool hit = (ddx * ddx + ddy * ddy <= rs * rs) &&
                       (isrow || jorig > i);
            if (hit) {
                int q = atomicAdd(&sqn[isrow], 1);
                if (q < CAPB)
                    (isrow ? sq1 : sq0)[q] = ibits | (unsigned)jorig;
            }
        }
    }
    __syncthreads();
    int n0 = min(sqn[0], CAPB), n1 = min(sqn[1], CAPB);
    if (tid == 0) sbase1 = atomicAdd(&g_mc.ctr, n1);
    __syncthreads();
    for (int t = tid; t < n1; t += 256) {
        int p2 = sbase1 + t;
        if (p2 < QCAP) g_qr[p2] = sq1[t];
    }

    for (int t = tid; t < n0 + n1; t += 256) {
        bool isrow = t >= n0;
        int s = isrow ? t - n0 : t;
        unsigned e = (isrow ? sq1 : sq0)[s];
        int a = (int)(e >> 10), j = (int)(e & 1023u);
        BP A, B;
        make_bp(A, isrow ? (pred + a * 7) : (gt + a * 8));
        make_bp(B, gt + j * 8);
        float dx = B.cx - A.cx, dy = B.cy - A.cy;
        float cc = fabsf(A.cr * B.cr + A.sr * B.sr);
        float ss = fabsf(A.sr * B.cr - A.cr * B.sr);
        bool sep =
            (fabsf(dx * A.cr + dy * A.sr)  > A.hdx + B.hdx * cc + B.hdy * ss + 1e-3f) ||
            (fabsf(-dx * A.sr + dy * A.cr) > A.hdy + B.hdx * ss + B.hdy * cc + 1e-3f) ||
            (fabsf(dx * B.cr + dy * B.sr)  > B.hdx + A.hdx * cc + A.hdy * ss + 1e-3f) ||
            (fabsf(-dx * B.sr + dy * B.cr) > B.hdy + A.hdx * ss + A.hdy * cc + 1e-3f);
        float inter = sep ? 0.0f : inter_area(A, B);
        if (!isrow) {
            float v = inter / fmaxf(A.area + B.area - inter, EPSV);
            if (v > 0.1f) {
                float la = labels[a], lj = labels[j];
                int lo = (la >= lj) ? a : j;     // a < j: ties keep a (score order)
                int hi = a + j - lo;
                atomicOr(&g_mc.mask[(lo >> 5) * NB + hi], 1u << (lo & 31));
            }
        } else {
            float oh = fmaxf(fminf(A.zhi, B.zhi) - fmaxf(A.zlo, B.zlo), 0.0f);
            float i3 = inter * oh;
            float v = i3 / fmaxf(A.vol + B.vol - i3, EPSV);
            int p2 = sbase1 + s;
            if (p2 < QCAP)
                g_rvkey[p2] =
                    ((unsigned long long)__float_as_uint(v) << 32) |
                    (unsigned long long)(0xFFFFFFFFu - (unsigned)j);
        }
    }
}

// ---------- k2: 1-barrier Jacobi fixpoint NMS + keep-filtered merge + decode ----------
__global__ void k_nms(float* __restrict__ out) {
    __shared__ unsigned keepA[32], keepB[32];
    __shared__ unsigned long long sbest[NB];
    __shared__ unsigned sword[SWCAP];
    __shared__ int salloc;
    __shared__ int chgc;
    int tid = threadIdx.x;   // orig gt index (column)
    unsigned nz = 0;
#pragma unroll
    for (int w = 0; w < 32; w++)
        nz |= (g_mc.mask[w * NB + tid] != 0u) ? (1u << w) : 0u;
    int cnt = __popc(nz);
    if (tid < 32) { keepA[tid] = 0xFFFFFFFFu; }
    sbest[tid] = 0xFFFFFFFFull;   // v=0, j=0
    if (tid == 0) { salloc = 0; chgc = 0; }
    __syncthreads();
    int base = cnt ? atomicAdd(&salloc, cnt) : 0;
    // pack word data into smem pool + word indices into 3 u64s (5 bits each)
    unsigned long long pk0 = 0, pk1 = 0, pk2 = 0;
    {
        unsigned r = nz;
        int k = 0;
        while (r) {
            int w = __ffs(r) - 1;
            r &= r - 1;
            if (base + k < SWCAP) sword[base + k] = g_mc.mask[w * NB + tid];
            unsigned long long wv = (unsigned long long)w;
            if (k < 12) pk0 |= wv << (5 * k);
            else if (k < 24) pk1 |= wv << (5 * (k - 12));
            else pk2 |= wv << (5 * (k - 24));
            k++;
        }
    }
    bool pooled = (base + cnt <= SWCAP);
    __syncthreads();
    unsigned* cur = keepA;
    unsigned* nxt = keepB;
    int prev = 0;
    for (int it = 0; it < NB; it++) {
        unsigned sup = 0;
#pragma unroll 4
        for (int k = 0; k < cnt; k++) {
            int w;
            if (k < 12)      w = (int)((pk0 >> (5 * k)) & 31);
            else if (k < 24) w = (int)((pk1 >> (5 * (k - 12))) & 31);
            else             w = (int)((pk2 >> (5 * (k - 24))) & 31);
            unsigned word = pooled ? sword[base + k] : g_mc.mask[w * NB + tid];
            sup |= word & cur[w];
        }
        unsigned bal = __ballot_sync(0xffffffffu, sup == 0u);
        if ((tid & 31) == 0) {
            nxt[tid >> 5] = bal;
            if (bal != cur[tid >> 5]) atomicAdd(&chgc, 1);
        }
        __syncthreads();
        int c = chgc;                 // monotone counter: no reset needed
        if (c == prev) break;         // cur holds the stable fixpoint
        prev = c;
        unsigned* tmp = cur; cur = nxt; nxt = tmp;
    }
    // merge row-pair keys filtered by final keep (cur)
    int nr = min(g_mc.ctr, QCAP);
    for (int t = tid; t < nr; t += NB) {
        unsigned e = g_qr[t];
        int j = (int)(e & 1023u);
        if ((cur[j >> 5] >> (j & 31)) & 1u)
            atomicMax(&sbest[e >> 10], g_rvkey[t]);
    }
    __syncthreads();
    unsigned long long key = sbest[tid];
    float mo = __uint_as_float((unsigned)(key >> 32));
    int j = (int)(0xFFFFFFFFu - (unsigned)(key & 0xFFFFFFFFull));
    mo = (mo > 0.75f) ? 1.0f : ((mo < 0.25f) ? 0.0f : mo);
    out[2 * NB + tid] = mo;
    out[3 * NB + tid] = (float)j;
}

extern "C" void kernel_launch(void* const* d_in, const int* in_sizes, int n_in,
                              void* d_out, int out_size) {
    const float* labels = (const float*)d_in[0];
    const float* pred   = (const float*)d_in[1];
    const float* gt     = (const float*)d_in[2];
    const float* cls    = (const float*)d_in[3];
    float* out = (float*)d_out;

    void* mcp = nullptr;
    cudaGetSymbolAddress(&mcp, g_mc);
    cudaMemsetAsync(mcp, 0, sizeof(MC), 0);

    k1<<<GEN_BLOCKS, 256>>>(labels, pred, gt, cls, out);
    k_nms<<<1, 1024>>>(out);
}

// round 14
// speedup vs baseline: 1.0738x; 1.0738x over previous
#include <cuda_runtime.h>
#include <math.h>

#define NB 1024
#define EPSV 1e-8f
#define QCAP 65536
#define CAPB 2048
#define NBINS 128
#define INVW (128.0f / 80.0f)
#define RMAX 3.55f
#define GEN_BLOCKS 128
#define MERGE_BLOCKS 64
#define SWCAP 6144

struct BP {
    float cx, cy, area, vol;
    float cr, sr, hdx, hdy;
    float zlo, zhi;
    float corx[4];
    float cory[4];
};

struct MC { unsigned mask[32 * NB]; int ctr; int done; };

__device__ MC g_mc;                    // suppression mask (orig space) + counters (memset 0)
__device__ unsigned g_qr[QCAP];        // row pairs (pred r, gt j) orig
__device__ unsigned long long g_rvkey[QCAP];
__device__ unsigned g_keep[32];        // final keep bits (orig space)
__device__ unsigned long long g_best[NB];  // init by k1 to 0x00000000FFFFFFFF

__device__ __forceinline__ void make_bp(BP& p, const float* b) {
    float x = b[0], y = b[1], z = b[2];
    float dx = b[3], dy = b[4], dz = b[5];
    float cr, sr;
    sincosf(b[6], &sr, &cr);
    p.cx = x; p.cy = y; p.cr = cr; p.sr = sr;
    p.hdx = 0.5f * dx; p.hdy = 0.5f * dy;
    p.area = dx * dy;
    p.vol = dx * dy * dz;
    p.zlo = z - 0.5f * dz; p.zhi = z + 0.5f * dz;
    const float sx[4] = {0.5f, 0.5f, -0.5f, -0.5f};
    const float sy[4] = {0.5f, -0.5f, -0.5f, 0.5f};
#pragma unroll
    for (int c = 0; c < 4; c++) {
        float lx = sx[c] * dx, ly = sy[c] * dy;
        p.corx[c] = lx * cr - ly * sr + x;
        p.cory[c] = lx * sr + ly * cr + y;
    }
}

__device__ __forceinline__ unsigned okey(float y, float x, int idx, unsigned msk) {
    float d = fabsf(x) + fabsf(y);
    float a = (d == 0.0f) ? 0.0f : copysignf(1.0f - x / d, y);
    unsigned u = __float_as_uint(a);
    u ^= (u & 0x80000000u) ? 0xFFFFFFFFu : 0x80000000u;
    return (u & msk) | (unsigned)idx;
}

// Reference-faithful rotated-rect intersection; tiered register bitonic sort.
__device__ float inter_area(const BP& A, const BP& B) {
    float px[24], py[24];
    int m = 0;
#pragma unroll
    for (int c = 0; c < 4; c++) {
        float dx = A.corx[c] - B.cx, dy = A.cory[c] - B.cy;
        float lx = dx * B.cr + dy * B.sr;
        float ly = -dx * B.sr + dy * B.cr;
        if (fabsf(lx) <= B.hdx + 1e-5f && fabsf(ly) <= B.hdy + 1e-5f) {
            px[m] = A.corx[c]; py[m] = A.cory[c]; m++;
        }
    }
#pragma unroll
    for (int c = 0; c < 4; c++) {
        float dx = B.corx[c] - A.cx, dy = B.cory[c] - A.cy;
        float lx = dx * A.cr + dy * A.sr;
        float ly = -dx * A.sr + dy * A.cr;
        if (fabsf(lx) <= A.hdx + 1e-5f && fabsf(ly) <= A.hdy + 1e-5f) {
            px[m] = B.corx[c]; py[m] = B.cory[c]; m++;
        }
    }
#pragma unroll
    for (int i = 0; i < 4; i++) {
        int i1 = (i + 1) & 3;
        float a0x = A.corx[i], a0y = A.cory[i];
        float d1x = A.corx[i1] - a0x, d1y = A.cory[i1] - a0y;
#pragma unroll
        for (int j = 0; j < 4; j++) {
            int j1 = (j + 1) & 3;
            float b0x = B.corx[j], b0y = B.cory[j];
            float d2x = B.corx[j1] - b0x, d2y = B.cory[j1] - b0y;
            float r0x = b0x - a0x, r0y = b0y - a0y;
            float den = d1x * d2y - d1y * d2x;
            if (fabsf(den) > EPSV) {
                float t = (r0x * d2y - r0y * d2x) / den;
                float u = (r0x * d1y - r0y * d1x) / den;
                if (t >= 0.f && t <= 1.f && u >= 0.f && u <= 1.f) {
                    px[m] = a0x + t * d1x; py[m] = a0y + t * d1y; m++;
                }
            }
        }
    }
    if (m < 3) return 0.0f;
    float sx = 0.f, sy = 0.f;
    for (int i = 0; i < m; i++) { sx += px[i]; sy += py[i]; }
    float inv = 1.0f / (float)m;
    float ctx = sx * inv, cty = sy * inv;
    float s = 0.f;

    if (m <= 16) {
        unsigned K[16];
#pragma unroll
        for (int i = 0; i < 16; i++)
            K[i] = (i < m) ? okey(py[i] - cty, px[i] - ctx, i, 0xFFFFFFF0u)
                           : (0xFFFFFFF0u | (unsigned)i);
#pragma unroll
        for (int kk = 2; kk <= 16; kk <<= 1)
#pragma unroll
            for (int jj = kk >> 1; jj > 0; jj >>= 1)
#pragma unroll
                for (int ii = 0; ii < 16; ii++) {
                    int ll = ii ^ jj;
                    if (ll > ii) {
                        bool up = ((ii & kk) == 0);
                        unsigned a2 = K[ii], b2 = K[ll];
                        if (up ? (a2 > b2) : (a2 < b2)) { K[ii] = b2; K[ll] = a2; }
                    }
                }
        int id0 = K[0] & 15;
        float x0 = px[id0] - ctx, y0 = py[id0] - cty;
        float xi = x0, yi = y0;
#pragma unroll
        for (int i = 0; i < 16; i++) {
            if (i < m) {
                float xj, yj;
                if (i + 1 < m) {
                    int idn = K[i + 1] & 15;
                    xj = px[idn] - ctx; yj = py[idn] - cty;
                } else { xj = x0; yj = y0; }
                s += xi * yj - yi * xj;
                xi = xj; yi = yj;
            }
        }
    } else {
        unsigned K[32];
#pragma unroll
        for (int i = 0; i < 32; i++)
            K[i] = (i < 24 && i < m) ? okey(py[i] - cty, px[i] - ctx, i, 0xFFFFFFE0u)
                                     : (0xFFFFFFE0u | (unsigned)i);
#pragma unroll
        for (int kk = 2; kk <= 32; kk <<= 1)
#pragma unroll
            for (int jj = kk >> 1; jj > 0; jj >>= 1)
#pragma unroll
                for (int ii = 0; ii < 32; ii++) {
                    int ll = ii ^ jj;
                    if (ll > ii) {
                        bool up = ((ii & kk) == 0);
                        unsigned a2 = K[ii], b2 = K[ll];
                        if (up ? (a2 > b2) : (a2 < b2)) { K[ii] = b2; K[ll] = a2; }
                    }
                }
        int id0 = K[0] & 31;
        float x0 = px[id0] - ctx, y0 = py[id0] - cty;
        float xi = x0, yi = y0;
#pragma unroll
        for (int i = 0; i < 24; i++) {
            if (i < m) {
                float xj, yj;
                if (i + 1 < m) {
                    int idn = K[i + 1] & 31;
                    xj = px[idn] - ctx; yj = py[idn] - cty;
                } else { xj = x0; yj = y0; }
                s += xi * yj - yi * xj;
                xi = xj; yi = yj;
            }
        }
    }
    return 0.5f * fabsf(s);
}

// ---------- k1: trivial outputs + g_best init + binned gen + fused heavy compute ----------
__global__ void k1(const float* __restrict__ labels,
                   const float* __restrict__ pred,
                   const float* __restrict__ gt,
                   const float* __restrict__ cls,
                   float* __restrict__ out) {
    __shared__ __align__(16) unsigned char sbuf[16384 + 2 * CAPB * 4];
    __shared__ int shist[NBINS];
    __shared__ int scur[NBINS];
    __shared__ int sqn[2];
    __shared__ int sbase1;
    int b = blockIdx.x;
    int tid = threadIdx.x;

    if (b < 4) {
        int t = b * 256 + tid;
        float sgm = 1.0f / (1.0f + expf(-cls[t]));
        float lb = labels[t];
        out[t] = (sgm > 0.55f && lb > 0.55f) ? 1.0f : 0.0f;
        out[NB + t] = lb;
        g_best[t] = 0xFFFFFFFFull;    // v=0, ~j=all-ones => decodes j=0
    }

    float4* sgt = (float4*)sbuf;
    unsigned* sq0 = (unsigned*)(sbuf + 16384);
    unsigned* sq1 = sq0 + CAPB;
    const float4* gt4 = (const float4*)gt;
    float4 st[4]; int sbin[4];
    if (tid < NBINS) shist[tid] = 0;
    if (tid < 2) sqn[tid] = 0;
    __syncthreads();
#pragma unroll
    for (int k = 0; k < 4; k++) {
        int i = tid + k * 256;
        float4 lo = gt4[2 * i];
        float4 hi = gt4[2 * i + 1];
        float rad = 0.5f * sqrtf(lo.w * lo.w + hi.x * hi.x) + 1e-3f;
        st[k] = make_float4(lo.x, lo.y, rad, __int_as_float(i));
        int bn = (int)((lo.x + 40.0f) * INVW);
        bn = min(max(bn, 0), NBINS - 1);
        sbin[k] = bn;
        atomicAdd(&shist[bn], 1);
    }
    __syncthreads();
    if (tid < 32) {
        int c0 = shist[tid * 4], c1 = shist[tid * 4 + 1];
        int c2 = shist[tid * 4 + 2], c3 = shist[tid * 4 + 3];
        int tot = c0 + c1 + c2 + c3;
        int pre = tot;
#pragma unroll
        for (int d = 1; d < 32; d <<= 1) {
            int v = __shfl_up_sync(0xffffffffu, pre, d);
            if (tid >= d) pre += v;
        }
        pre -= tot;
        shist[tid * 4] = pre;          scur[tid * 4] = pre;
        shist[tid * 4 + 1] = pre + c0; scur[tid * 4 + 1] = pre + c0;
        shist[tid * 4 + 2] = pre + c0 + c1; scur[tid * 4 + 2] = pre + c0 + c1;
        shist[tid * 4 + 3] = pre + c0 + c1 + c2; scur[tid * 4 + 3] = pre + c0 + c1 + c2;
    }
    __syncthreads();
#pragma unroll
    for (int k = 0; k < 4; k++) {
        int pos = atomicAdd(&scur[sbin[k]], 1);
        sgt[pos] = st[k];
    }
    __syncthreads();

    int lane = tid & 31;
#pragma unroll
    for (int tk = 0; tk < 2; tk++) {
        int task = (b * 8 + (tid >> 5)) * 2 + tk;
        int isrow = task >> 10;
        int i = task & 1023;
        float ax, ay, ar;
        if (isrow) {
            const float* p = pred + i * 7;
            ax = p[0]; ay = p[1];
            ar = 0.5f * sqrtf(p[3] * p[3] + p[4] * p[4]) + 1e-3f;
        } else {
            float4 lo = gt4[2 * i];
            float4 hi = gt4[2 * i + 1];
            ax = lo.x; ay = lo.y;
            ar = 0.5f * sqrtf(lo.w * lo.w + hi.x * hi.x) + 1e-3f;
        }
        float reach = ar + RMAX;
        int blo = max(0, (int)((ax - reach + 40.0f) * INVW));
        int bhi = min(NBINS - 1, (int)((ax + reach + 40.0f) * INVW));
        int pstart = shist[blo];
        int pend = (bhi == NBINS - 1) ? NB : shist[bhi + 1];
        unsigned ibits = (unsigned)i << 10;
        for (int p2 = pstart + lane; p2 < pend; p2 += 32) {
            float4 bb = sgt[p2];
            float ddx = ax - bb.x, ddy = ay - bb.y;
            float rs = ar + bb.z;
            int jorig = __float_as_int(bb.w);
            bool hit = (ddx * ddx + ddy * ddy <= rs * rs) &&
                       (isrow || jorig > i);
            if (hit) {
                int q = atomicAdd(&sqn[isrow], 1);
                if (q < CAPB)
                    (isrow ? sq1 : sq0)[q] = ibits | (unsigned)jorig;
            }
        }
    }
    __syncthreads();
    int n0 = min(sqn[0], CAPB), n1 = min(sqn[1], CAPB);
    if (tid == 0) sbase1 = atomicAdd(&g_mc.ctr, n1);
    __syncthreads();
    for (int t = tid; t < n1; t += 256) {
        int p2 = sbase1 + t;
        if (p2 < QCAP) g_qr[p2] = sq1[t];
    }

    for (int t = tid; t < n0 + n1; t += 256) {
        bool isrow = t >= n0;
        int s = isrow ? t - n0 : t;
        unsigned e = (isrow ? sq1 : sq0)[s];
        int a = (int)(e >> 10), j = (int)(e & 1023u);
        BP A, B;
        make_bp(A, isrow ? (pred + a * 7) : (gt + a * 8));
        make_bp(B, gt + j * 8);
        float dx = B.cx - A.cx, dy = B.cy - A.cy;
        float cc = fabsf(A.cr * B.cr + A.sr * B.sr);
        float ss = fabsf(A.sr * B.cr - A.cr * B.sr);
        bool sep =
            (fabsf(dx * A.cr + dy * A.sr)  > A.hdx + B.hdx * cc + B.hdy * ss + 1e-3f) ||
            (fabsf(-dx * A.sr + dy * A.cr) > A.hdy + B.hdx * ss + B.hdy * cc + 1e-3f) ||
            (fabsf(dx * B.cr + dy * B.sr)  > B.hdx + A.hdx * cc + A.hdy * ss + 1e-3f) ||
            (fabsf(-dx * B.sr + dy * B.cr) > B.hdy + A.hdx * ss + A.hdy * cc + 1e-3f);
        float inter = sep ? 0.0f : inter_area(A, B);
        if (!isrow) {
            float v = inter / fmaxf(A.area + B.area - inter, EPSV);
            if (v > 0.1f) {
                float la = labels[a], lj = labels[j];
                int lo = (la >= lj) ? a : j;     // a < j: ties keep a (score order)
                int hi = a + j - lo;
                atomicOr(&g_mc.mask[(lo >> 5) * NB + hi], 1u << (lo & 31));
            }
        } else {
            float oh = fmaxf(fminf(A.zhi, B.zhi) - fmaxf(A.zlo, B.zlo), 0.0f);
            float i3 = inter * oh;
            float v = i3 / fmaxf(A.vol + B.vol - i3, EPSV);
            int p2 = sbase1 + s;
            if (p2 < QCAP)
                g_rvkey[p2] =
                    ((unsigned long long)__float_as_uint(v) << 32) |
                    (unsigned long long)(0xFFFFFFFFu - (unsigned)j);
        }
    }
}

// ---------- k2: Jacobi fixpoint NMS only (1 block) ----------
__global__ void k_nms() {
    __shared__ unsigned keepA[32], keepB[32];
    __shared__ unsigned sword[SWCAP];
    __shared__ int salloc;
    __shared__ int chgc;
    int tid = threadIdx.x;   // orig gt index (column)
    unsigned tmp[32];
    unsigned nz = 0;
#pragma unroll
    for (int w = 0; w < 32; w++) {
        tmp[w] = g_mc.mask[w * NB + tid];
        nz |= (tmp[w] != 0u) ? (1u << w) : 0u;
    }
    int cnt = __popc(nz);
    if (tid < 32) keepA[tid] = 0xFFFFFFFFu;
    if (tid == 0) { salloc = 0; chgc = 0; }
    __syncthreads();
    int base = cnt ? atomicAdd(&salloc, cnt) : 0;
    unsigned long long pk0 = 0, pk1 = 0, pk2 = 0;
    {
        int k = 0;
#pragma unroll
        for (int w = 0; w < 32; w++) {
            if ((nz >> w) & 1u) {
                if (base + k < SWCAP) sword[base + k] = tmp[w];
                unsigned long long wv = (unsigned long long)w;
                if (k < 12) pk0 |= wv << (5 * k);
                else if (k < 24) pk1 |= wv << (5 * (k - 12));
                else pk2 |= wv << (5 * (k - 24));
                k++;
            }
        }
    }
    bool pooled = (base + cnt <= SWCAP);
    __syncthreads();
    unsigned* cur = keepA;
    unsigned* nxt = keepB;
    int prev = 0;
    for (int it = 0; it < NB; it++) {
        unsigned sup = 0;
#pragma unroll 4
        for (int k = 0; k < cnt; k++) {
            int w;
            if (k < 12)      w = (int)((pk0 >> (5 * k)) & 31);
            else if (k < 24) w = (int)((pk1 >> (5 * (k - 12))) & 31);
            else             w = (int)((pk2 >> (5 * (k - 24))) & 31);
            unsigned word = pooled ? sword[base + k] : g_mc.mask[w * NB + tid];
            sup |= word & cur[w];
        }
        unsigned bal = __ballot_sync(0xffffffffu, sup == 0u);
        if ((tid & 31) == 0) {
            nxt[tid >> 5] = bal;
            if (bal != cur[tid >> 5]) atomicAdd(&chgc, 1);
        }
        __syncthreads();
        int c = chgc;
        if (c == prev) break;
        prev = c;
        unsigned* t2 = cur; cur = nxt; nxt = t2;
    }
    if (tid < 32) g_keep[tid] = cur[tid];
}

// ---------- k3: parallel keep-filtered merge + last-block decode ----------
__global__ void k_merge(float* __restrict__ out) {
    __shared__ unsigned skeep[32];
    __shared__ int islast;
    int tid = threadIdx.x;
    if (tid < 32) skeep[tid] = g_keep[tid];
    __syncthreads();
    int nr = min(g_mc.ctr, QCAP);
    for (int t = blockIdx.x * 256 + tid; t < nr; t += gridDim.x * 256) {
        unsigned e = g_qr[t];
        int j = (int)(e & 1023u);
        if ((skeep[j >> 5] >> (j & 31)) & 1u)
            atomicMax(&g_best[e >> 10], g_rvkey[t]);
    }
    __threadfence();
    __syncthreads();
    if (tid == 0) {
        int v = atomicAdd(&g_mc.done, 1);
        islast = (v == (int)gridDim.x - 1);
    }
    __syncthreads();
    if (islast) {
        for (int i = tid; i < NB; i += 256) {
            unsigned long long key = g_best[i];
            float mo = __uint_as_float((unsigned)(key >> 32));
            int j = (int)(0xFFFFFFFFu - (unsigned)(key & 0xFFFFFFFFull));
            mo = (mo > 0.75f) ? 1.0f : ((mo < 0.25f) ? 0.0f : mo);
            out[2 * NB + i] = mo;
            out[3 * NB + i] = (float)j;
        }
    }
}

extern "C" void kernel_launch(void* const* d_in, const int* in_sizes, int n_in,
                              void* d_out, int out_size) {
    const float* labels = (const float*)d_in[0];
    const float* pred   = (const float*)d_in[1];
    const float* gt     = (const float*)d_in[2];
    const float* cls    = (const float*)d_in[3];
    float* out = (float*)d_out;

    void* mcp = nullptr;
    cudaGetSymbolAddress(&mcp, g_mc);
    cudaMemsetAsync(mcp, 0, sizeof(MC), 0);

    k1<<<GEN_BLOCKS, 256>>>(labels, pred, gt, cls, out);
    k_nms<<<1, 1024>>>();
    k_merge<<<MERGE_BLOCKS, 256>>>(out);
}